// round 11
// baseline (speedup 1.0000x reference)
#include <cuda_runtime.h>
#include <cuda_bf16.h>
#include <math.h>

// Fixed problem shapes
#define B_   64
#define M_   80
#define TOUT 2000
#define TIN  400

#define N_MEL   (B_ * M_ * TOUT)          // 10,240,000
#define N_MEL4  (N_MEL / 4)               // 2,560,000
#define N_GATE  (B_ * TOUT)               // 128,000
#define N_GATE4 (N_GATE / 4)              // 32,000
#define N_ROWS  (B_ * TOUT)               // 128,000 alignment rows
#define N_AL4   (N_ROWS * 100)            // 12,800,000 float4
#define TIN4    (TIN / 4)                 // 100 float4 per row

#define INV2SIG2 3.125f                   // 1/(2*0.4^2)
#define BAND     2.45f                    // exp(-3.125*2.45^2) ~ 6e-9 (negligible)

// One wave: 148 SMs x occ 8 = 1184 identical blocks; every block runs every
// phase over its own stripe (perfect balance). 32-reg cap enables occ 8.
#define G_TOTAL 1184
#define NTHREAD 256
#define TSTRIDE (G_TOTAL * NTHREAD)       // 303,104 threads

// Accumulators: 0=mel1, 1=mel2, 2=gate, 3=att, 4=ga
// Zero-initialized statics; last finishing block re-zeroes after reading.
__device__ double g_acc[5];
__device__ unsigned int g_done;

__device__ __forceinline__ float warp_sum(float v) {
    #pragma unroll
    for (int o = 16; o > 0; o >>= 1)
        v += __shfl_xor_sync(0xFFFFFFFFu, v, o);
    return v;
}

__device__ __forceinline__ float bce1(float x, float z) {
    return fmaxf(x, 0.0f) - x * z + log1pf(expf(-fabsf(x)));
}

// per-float4 align contribution (att + ga masked sums)
__device__ __forceinline__ void align_elem(float4 a, int idx,
                                           const int* __restrict__ s_li,
                                           const int* __restrict__ s_lo,
                                           float& s_att, float& s_ga) {
    unsigned uidx = (unsigned)idx;
    unsigned j4  = uidx % TIN4;
    unsigned row = uidx / TIN4;
    unsigned b   = row / TOUT;
    int      i   = (int)(row - b * TOUT);
    int      j0  = (int)(j4 << 2);

    float sfull = (a.x + a.y) + (a.z + a.w);

    // att: sum over j < i
    if (j0 + 4 <= i) {
        s_att += sfull;
    } else if (j0 < i) {
        s_att += ((j0     < i ? a.x : 0.0f) + (j0 + 1 < i ? a.y : 0.0f))
               + ((j0 + 2 < i ? a.z : 0.0f) + (j0 + 3 < i ? a.w : 0.0f));
    }

    // ga main: valid region (i<lo, j<li); w==1 outside the narrow exp band
    int limG = (i < s_lo[b]) ? s_li[b] : 0;
    if (j0 + 4 <= limG) {
        s_ga += sfull;
    } else if (j0 < limG) {
        s_ga += ((j0     < limG ? a.x : 0.0f) + (j0 + 1 < limG ? a.y : 0.0f))
              + ((j0 + 2 < limG ? a.z : 0.0f) + (j0 + 3 < limG ? a.w : 0.0f));
    }
}

__global__ void __launch_bounds__(NTHREAD, 8)
fused_kernel(const float4* __restrict__ mo,
             const float4* __restrict__ mp,
             const float4* __restrict__ mt,
             const float4* __restrict__ go,
             const float4* __restrict__ gt,
             const float4* __restrict__ al,
             const float*  __restrict__ al_s,
             const int*    __restrict__ in_len,
             const int*    __restrict__ out_len,
             float*        __restrict__ out) {
    __shared__ int s_li[B_], s_lo[B_];
    if (threadIdx.x < B_) {
        s_li[threadIdx.x] = in_len[threadIdx.x];
        s_lo[threadIdx.x] = out_len[threadIdx.x];
    }
    __syncthreads();

    const int gtid = blockIdx.x * NTHREAD + threadIdx.x;

    // ======== Phase 1: Gate BCE (tiny) ========
    float s_gate = 0.0f;
    for (int i = gtid; i < N_GATE4; i += TSTRIDE) {
        float4 x = __ldcs(&go[i]);
        float4 z = __ldcs(&gt[i]);
        s_gate += bce1(x.x, z.x) + bce1(x.y, z.y) + bce1(x.z, z.z) + bce1(x.w, z.w);
    }

    // ======== Phase 2: guided-attention band correction ========
    // -sum a*exp(-d^2/(2 sigma^2)); only |i - j*lo/li| <= BAND contributes.
    float s_corr = 0.0f;
    for (int row = gtid; row < N_ROWS; row += TSTRIDE) {
        int b = row / TOUT;
        int i = row - b * TOUT;
        int li = s_li[b];
        int lo = s_lo[b];
        if (i < lo) {
            float fli = (float)li, flo = (float)lo, fi = (float)i;
            float inv_scale = __fdividef(fli, flo);   // li/lo
            float scale     = __fdividef(flo, fli);   // lo/li
            int j0c = (int)floorf((fi - BAND) * inv_scale);
            const float* rp = al_s + (long)row * TIN;
            #pragma unroll
            for (int k = 0; k < 4; k++) {
                int j = j0c + k;
                if (j >= 0 && j < li) {
                    float d = fmaf((float)j, -scale, fi);
                    float e = __expf(-d * d * INV2SIG2);
                    s_corr += __ldg(&rp[j]) * e;
                }
            }
        }
    }

    // ======== Phase 3: Mel L1 (decoder + postnet), 2x unrolled, streaming ========
    float s1 = 0.0f, s2 = 0.0f;
    {
        int i = gtid;
        for (; i + TSTRIDE < N_MEL4; i += 2 * TSTRIDE) {
            float4 a0 = __ldcs(&mo[i]), a1 = __ldcs(&mo[i + TSTRIDE]);
            float4 t0 = __ldcs(&mt[i]), t1 = __ldcs(&mt[i + TSTRIDE]);
            float4 p0 = __ldcs(&mp[i]), p1 = __ldcs(&mp[i + TSTRIDE]);
            s1 += fabsf(a0.x - t0.x) + fabsf(a0.y - t0.y) + fabsf(a0.z - t0.z) + fabsf(a0.w - t0.w);
            s2 += fabsf(p0.x - t0.x) + fabsf(p0.y - t0.y) + fabsf(p0.z - t0.z) + fabsf(p0.w - t0.w);
            s1 += fabsf(a1.x - t1.x) + fabsf(a1.y - t1.y) + fabsf(a1.z - t1.z) + fabsf(a1.w - t1.w);
            s2 += fabsf(p1.x - t1.x) + fabsf(p1.y - t1.y) + fabsf(p1.z - t1.z) + fabsf(p1.w - t1.w);
        }
        for (; i < N_MEL4; i += TSTRIDE) {
            float4 a = __ldcs(&mo[i]), p = __ldcs(&mp[i]), t = __ldcs(&mt[i]);
            s1 += fabsf(a.x - t.x) + fabsf(a.y - t.y) + fabsf(a.z - t.z) + fabsf(a.w - t.w);
            s2 += fabsf(p.x - t.x) + fabsf(p.y - t.y) + fabsf(p.z - t.z) + fabsf(p.w - t.w);
        }
    }

    // ======== Phase 4: Alignments main pass, warp-contiguous float4, 4x batched ========
    float s_att = 0.0f, s_ga = 0.0f;
    {
        int idx = gtid;
        for (; idx + 3 * TSTRIDE < N_AL4; idx += 4 * TSTRIDE) {
            float4 a0 = __ldcs(&al[idx]);
            float4 a1 = __ldcs(&al[idx + TSTRIDE]);
            float4 a2 = __ldcs(&al[idx + 2 * TSTRIDE]);
            float4 a3 = __ldcs(&al[idx + 3 * TSTRIDE]);
            align_elem(a0, idx,               s_li, s_lo, s_att, s_ga);
            align_elem(a1, idx + TSTRIDE,     s_li, s_lo, s_att, s_ga);
            align_elem(a2, idx + 2 * TSTRIDE, s_li, s_lo, s_att, s_ga);
            align_elem(a3, idx + 3 * TSTRIDE, s_li, s_lo, s_att, s_ga);
        }
        for (; idx < N_AL4; idx += TSTRIDE) {
            float4 a = __ldcs(&al[idx]);
            align_elem(a, idx, s_li, s_lo, s_att, s_ga);
        }
    }
    s_ga -= s_corr;

    // ======== Block reduce all 5 sums, atomics, last-block finalize ========
    __shared__ float sh[5][8];
    int lane = threadIdx.x & 31;
    int wid  = threadIdx.x >> 5;
    float v0 = warp_sum(s1);
    float v1 = warp_sum(s2);
    float v2 = warp_sum(s_gate);
    float v3 = warp_sum(s_att);
    float v4 = warp_sum(s_ga);
    if (lane == 0) {
        sh[0][wid] = v0; sh[1][wid] = v1; sh[2][wid] = v2;
        sh[3][wid] = v3; sh[4][wid] = v4;
    }
    __syncthreads();
    if (wid == 0) {
        v0 = warp_sum((lane < 8) ? sh[0][lane] : 0.0f);
        v1 = warp_sum((lane < 8) ? sh[1][lane] : 0.0f);
        v2 = warp_sum((lane < 8) ? sh[2][lane] : 0.0f);
        v3 = warp_sum((lane < 8) ? sh[3][lane] : 0.0f);
        v4 = warp_sum((lane < 8) ? sh[4][lane] : 0.0f);
        if (lane == 0) {
            atomicAdd(&g_acc[0], (double)v0);
            atomicAdd(&g_acc[1], (double)v1);
            atomicAdd(&g_acc[2], (double)v2);
            atomicAdd(&g_acc[3], (double)v3);
            atomicAdd(&g_acc[4], (double)v4);
            __threadfence();
            unsigned int t = atomicAdd(&g_done, 1u);
            if (t == (unsigned)(G_TOTAL - 1)) {
                volatile double* acc = g_acc;
                double mel  = (acc[0] + acc[1]) / (double)N_MEL;
                double gate = acc[2] / (double)N_GATE;
                double att  = acc[3] / (double)B_;
                double ga   = acc[4] / (double)B_;
                double total = mel + gate + 0.1 * att + 0.1 * ga;
                out[0] = (float)total;
                out[1] = (float)mel;
                out[2] = (float)gate;
                out[3] = (float)att;
                out[4] = (float)ga;
                acc[0] = 0.0; acc[1] = 0.0; acc[2] = 0.0; acc[3] = 0.0; acc[4] = 0.0;
                g_done = 0u;
                __threadfence();
            }
        }
    }
}

extern "C" void kernel_launch(void* const* d_in, const int* in_sizes, int n_in,
                              void* d_out, int out_size) {
    const float* mel_out         = (const float*)d_in[0];
    const float* mel_out_postnet = (const float*)d_in[1];
    const float* gate_out        = (const float*)d_in[2];
    const float* alignments      = (const float*)d_in[3];
    const float* mel_target      = (const float*)d_in[4];
    const float* gate_target     = (const float*)d_in[5];
    const int*   input_lengths   = (const int*)d_in[6];
    const int*   output_lengths  = (const int*)d_in[7];
    float* out = (float*)d_out;

    fused_kernel<<<G_TOTAL, NTHREAD>>>((const float4*)mel_out,
                                       (const float4*)mel_out_postnet,
                                       (const float4*)mel_target,
                                       (const float4*)gate_out,
                                       (const float4*)gate_target,
                                       (const float4*)alignments,
                                       alignments,
                                       input_lengths, output_lengths,
                                       out);
}

// round 12
// speedup vs baseline: 1.1053x; 1.1053x over previous
#include <cuda_runtime.h>
#include <cuda_bf16.h>
#include <math.h>

// Fixed problem shapes
#define B_   64
#define M_   80
#define TOUT 2000
#define TIN  400

#define N_MEL   (B_ * M_ * TOUT)          // 10,240,000
#define N_MEL4  (N_MEL / 4)               // 2,560,000
#define N_GATE  (B_ * TOUT)               // 128,000
#define N_GATE4 (N_GATE / 4)              // 32,000
#define N_ROWS  (B_ * TOUT)               // 128,000 alignment rows
#define N_AL4   (N_ROWS * 100)            // 12,800,000 float4
#define TIN4    (TIN / 4)                 // 100 float4 per row

#define INV2SIG2 3.125f                   // 1/(2*0.4^2)
#define BAND     2.45f                    // exp(-3.125*2.45^2) ~ 6e-9 (negligible)

// One wave: 148 SMs x occ 6 = 888 identical blocks; every block runs every
// phase over its own stripe (perfect balance, no section tail).
#define G_TOTAL 888
#define NTHREAD 256
#define TSTRIDE (G_TOTAL * NTHREAD)       // 227,328 threads

// Accumulators: 0=mel1, 1=mel2, 2=gate, 3=att, 4=ga
// Zero-initialized statics; last finishing block re-zeroes after reading.
__device__ double g_acc[5];
__device__ unsigned int g_done;

__device__ __forceinline__ float warp_sum(float v) {
    #pragma unroll
    for (int o = 16; o > 0; o >>= 1)
        v += __shfl_xor_sync(0xFFFFFFFFu, v, o);
    return v;
}

__device__ __forceinline__ float bce1(float x, float z) {
    return fmaxf(x, 0.0f) - x * z + log1pf(expf(-fabsf(x)));
}

// per-float4 align contribution (att + ga masked sums)
__device__ __forceinline__ void align_elem(float4 a, int idx,
                                           const int* __restrict__ s_li,
                                           const int* __restrict__ s_lo,
                                           float& s_att, float& s_ga) {
    unsigned uidx = (unsigned)idx;
    unsigned j4  = uidx % TIN4;
    unsigned row = uidx / TIN4;
    unsigned b   = row / TOUT;
    int      i   = (int)(row - b * TOUT);
    int      j0  = (int)(j4 << 2);

    float sfull = (a.x + a.y) + (a.z + a.w);

    // att: sum over j < i
    if (j0 + 4 <= i) {
        s_att += sfull;
    } else if (j0 < i) {
        s_att += ((j0     < i ? a.x : 0.0f) + (j0 + 1 < i ? a.y : 0.0f))
               + ((j0 + 2 < i ? a.z : 0.0f) + (j0 + 3 < i ? a.w : 0.0f));
    }

    // ga main: valid region (i<lo, j<li); w==1 outside the narrow exp band
    int limG = (i < s_lo[b]) ? s_li[b] : 0;
    if (j0 + 4 <= limG) {
        s_ga += sfull;
    } else if (j0 < limG) {
        s_ga += ((j0     < limG ? a.x : 0.0f) + (j0 + 1 < limG ? a.y : 0.0f))
              + ((j0 + 2 < limG ? a.z : 0.0f) + (j0 + 3 < limG ? a.w : 0.0f));
    }
}

// guided-attention band correction for this thread's row stripe:
// sum a*exp(-d^2/(2 sigma^2)); only |i - j*lo/li| <= BAND contributes.
__device__ __forceinline__ float corr_phase(const float* __restrict__ al_s,
                                            const int* __restrict__ s_li,
                                            const int* __restrict__ s_lo,
                                            int gtid) {
    float s_corr = 0.0f;
    for (int row = gtid; row < N_ROWS; row += TSTRIDE) {
        int b = row / TOUT;
        int i = row - b * TOUT;
        int li = s_li[b];
        int lo = s_lo[b];
        if (i < lo) {
            float fli = (float)li, flo = (float)lo, fi = (float)i;
            float inv_scale = __fdividef(fli, flo);   // li/lo
            float scale     = __fdividef(flo, fli);   // lo/li
            int j0c = (int)floorf((fi - BAND) * inv_scale);
            const float* rp = al_s + (long)row * TIN;
            #pragma unroll
            for (int k = 0; k < 4; k++) {
                int j = j0c + k;
                if (j >= 0 && j < li) {
                    float d = fmaf((float)j, -scale, fi);
                    float e = __expf(-d * d * INV2SIG2);
                    s_corr += __ldg(&rp[j]) * e;
                }
            }
        }
    }
    return s_corr;
}

__global__ void __launch_bounds__(NTHREAD, 6)
fused_kernel(const float4* __restrict__ mo,
             const float4* __restrict__ mp,
             const float4* __restrict__ mt,
             const float4* __restrict__ go,
             const float4* __restrict__ gt,
             const float4* __restrict__ al,
             const float*  __restrict__ al_s,
             const int*    __restrict__ in_len,
             const int*    __restrict__ out_len,
             float*        __restrict__ out) {
    __shared__ int s_li[B_], s_lo[B_];
    if (threadIdx.x < B_) {
        s_li[threadIdx.x] = in_len[threadIdx.x];
        s_lo[threadIdx.x] = out_len[threadIdx.x];
    }
    __syncthreads();

    const int  gtid = blockIdx.x * NTHREAD + threadIdx.x;
    const bool even = (blockIdx.x & 1) == 0;

    // ======== Phase 1: Gate BCE (tiny) ========
    float s_gate = 0.0f;
    for (int i = gtid; i < N_GATE4; i += TSTRIDE) {
        float4 x = __ldcs(&go[i]);
        float4 z = __ldcs(&gt[i]);
        s_gate += bce1(x.x, z.x) + bce1(x.y, z.y) + bce1(x.z, z.z) + bce1(x.w, z.w);
    }

    // ======== Phase 2: Mel L1 (decoder + postnet), 2x unrolled, streaming ========
    // Pure stream first: chip-wide full-BW at kernel start.
    float s1 = 0.0f, s2 = 0.0f;
    {
        int i = gtid;
        for (; i + TSTRIDE < N_MEL4; i += 2 * TSTRIDE) {
            float4 a0 = __ldcs(&mo[i]), a1 = __ldcs(&mo[i + TSTRIDE]);
            float4 t0 = __ldcs(&mt[i]), t1 = __ldcs(&mt[i + TSTRIDE]);
            float4 p0 = __ldcs(&mp[i]), p1 = __ldcs(&mp[i + TSTRIDE]);
            s1 += fabsf(a0.x - t0.x) + fabsf(a0.y - t0.y) + fabsf(a0.z - t0.z) + fabsf(a0.w - t0.w);
            s2 += fabsf(p0.x - t0.x) + fabsf(p0.y - t0.y) + fabsf(p0.z - t0.z) + fabsf(p0.w - t0.w);
            s1 += fabsf(a1.x - t1.x) + fabsf(a1.y - t1.y) + fabsf(a1.z - t1.z) + fabsf(a1.w - t1.w);
            s2 += fabsf(p1.x - t1.x) + fabsf(p1.y - t1.y) + fabsf(p1.z - t1.z) + fabsf(p1.w - t1.w);
        }
        for (; i < N_MEL4; i += TSTRIDE) {
            float4 a = __ldcs(&mo[i]), p = __ldcs(&mp[i]), t = __ldcs(&mt[i]);
            s1 += fabsf(a.x - t.x) + fabsf(a.y - t.y) + fabsf(a.z - t.z) + fabsf(a.w - t.w);
            s2 += fabsf(p.x - t.x) + fabsf(p.y - t.y) + fabsf(p.z - t.z) + fabsf(p.w - t.w);
        }
    }

    // ======== Phase 3a: corr (even blocks) — staggered latency-bound phase ========
    float s_corr = 0.0f;
    if (even) s_corr = corr_phase(al_s, s_li, s_lo, gtid);

    // ======== Phase 4: Alignments main pass, warp-contiguous float4, 4x batched ========
    float s_att = 0.0f, s_ga = 0.0f;
    {
        int idx = gtid;
        for (; idx + 3 * TSTRIDE < N_AL4; idx += 4 * TSTRIDE) {
            float4 a0 = __ldcs(&al[idx]);
            float4 a1 = __ldcs(&al[idx + TSTRIDE]);
            float4 a2 = __ldcs(&al[idx + 2 * TSTRIDE]);
            float4 a3 = __ldcs(&al[idx + 3 * TSTRIDE]);
            align_elem(a0, idx,               s_li, s_lo, s_att, s_ga);
            align_elem(a1, idx + TSTRIDE,     s_li, s_lo, s_att, s_ga);
            align_elem(a2, idx + 2 * TSTRIDE, s_li, s_lo, s_att, s_ga);
            align_elem(a3, idx + 3 * TSTRIDE, s_li, s_lo, s_att, s_ga);
        }
        for (; idx < N_AL4; idx += TSTRIDE) {
            float4 a = __ldcs(&al[idx]);
            align_elem(a, idx, s_li, s_lo, s_att, s_ga);
        }
    }

    // ======== Phase 3b: corr (odd blocks) ========
    if (!even) s_corr = corr_phase(al_s, s_li, s_lo, gtid);

    s_ga -= s_corr;

    // ======== Block reduce all 5 sums, atomics, last-block finalize ========
    __shared__ float sh[5][8];
    int lane = threadIdx.x & 31;
    int wid  = threadIdx.x >> 5;
    float v0 = warp_sum(s1);
    float v1 = warp_sum(s2);
    float v2 = warp_sum(s_gate);
    float v3 = warp_sum(s_att);
    float v4 = warp_sum(s_ga);
    if (lane == 0) {
        sh[0][wid] = v0; sh[1][wid] = v1; sh[2][wid] = v2;
        sh[3][wid] = v3; sh[4][wid] = v4;
    }
    __syncthreads();
    if (wid == 0) {
        v0 = warp_sum((lane < 8) ? sh[0][lane] : 0.0f);
        v1 = warp_sum((lane < 8) ? sh[1][lane] : 0.0f);
        v2 = warp_sum((lane < 8) ? sh[2][lane] : 0.0f);
        v3 = warp_sum((lane < 8) ? sh[3][lane] : 0.0f);
        v4 = warp_sum((lane < 8) ? sh[4][lane] : 0.0f);
        if (lane == 0) {
            atomicAdd(&g_acc[0], (double)v0);
            atomicAdd(&g_acc[1], (double)v1);
            atomicAdd(&g_acc[2], (double)v2);
            atomicAdd(&g_acc[3], (double)v3);
            atomicAdd(&g_acc[4], (double)v4);
            __threadfence();
            unsigned int t = atomicAdd(&g_done, 1u);
            if (t == (unsigned)(G_TOTAL - 1)) {
                volatile double* acc = g_acc;
                double mel  = (acc[0] + acc[1]) / (double)N_MEL;
                double gate = acc[2] / (double)N_GATE;
                double att  = acc[3] / (double)B_;
                double ga   = acc[4] / (double)B_;
                double total = mel + gate + 0.1 * att + 0.1 * ga;
                out[0] = (float)total;
                out[1] = (float)mel;
                out[2] = (float)gate;
                out[3] = (float)att;
                out[4] = (float)ga;
                acc[0] = 0.0; acc[1] = 0.0; acc[2] = 0.0; acc[3] = 0.0; acc[4] = 0.0;
                g_done = 0u;
                __threadfence();
            }
        }
    }
}

extern "C" void kernel_launch(void* const* d_in, const int* in_sizes, int n_in,
                              void* d_out, int out_size) {
    const float* mel_out         = (const float*)d_in[0];
    const float* mel_out_postnet = (const float*)d_in[1];
    const float* gate_out        = (const float*)d_in[2];
    const float* alignments      = (const float*)d_in[3];
    const float* mel_target      = (const float*)d_in[4];
    const float* gate_target     = (const float*)d_in[5];
    const int*   input_lengths   = (const int*)d_in[6];
    const int*   output_lengths  = (const int*)d_in[7];
    float* out = (float*)d_out;

    fused_kernel<<<G_TOTAL, NTHREAD>>>((const float4*)mel_out,
                                       (const float4*)mel_out_postnet,
                                       (const float4*)mel_target,
                                       (const float4*)gate_out,
                                       (const float4*)gate_target,
                                       (const float4*)alignments,
                                       alignments,
                                       input_lengths, output_lengths,
                                       out);
}

// round 14
// speedup vs baseline: 1.1732x; 1.0614x over previous
#include <cuda_runtime.h>
#include <cuda_bf16.h>
#include <math.h>

// Fixed problem shapes
#define B_   64
#define M_   80
#define TOUT 2000
#define TIN  400

#define N_MEL   (B_ * M_ * TOUT)          // 10,240,000
#define N_MEL4  (N_MEL / 4)               // 2,560,000
#define N_GATE  (B_ * TOUT)               // 128,000
#define N_GATE4 (N_GATE / 4)              // 32,000
#define N_ROWS  (B_ * TOUT)               // 128,000 alignment rows
#define N_AL4   (N_ROWS * 100)            // 12,800,000 float4
#define TIN4    (TIN / 4)                 // 100 float4 per row

#define INV2SIG2 3.125f                   // 1/(2*0.4^2)
#define BAND     2.45f                    // exp(-3.125*2.45^2) ~ 6e-9 (negligible)

// One wave: 148 SMs x occ 5 = 740 identical blocks; every block runs every
// phase over its own stripe. Occ 5 buys registers for a 6-deep batched
// align loop (30.7KB outstanding/SM > ~25.6KB BW*latency requirement).
#define G_TOTAL 740
#define NTHREAD 256
#define TSTRIDE (G_TOTAL * NTHREAD)       // 189,440 threads

// Accumulators: 0=mel1, 1=mel2, 2=gate, 3=att, 4=ga
// Zero-initialized statics; last finishing block re-zeroes after reading.
__device__ double g_acc[5];
__device__ unsigned int g_done;

__device__ __forceinline__ float warp_sum(float v) {
    #pragma unroll
    for (int o = 16; o > 0; o >>= 1)
        v += __shfl_xor_sync(0xFFFFFFFFu, v, o);
    return v;
}

__device__ __forceinline__ float bce1(float x, float z) {
    return fmaxf(x, 0.0f) - x * z + log1pf(expf(-fabsf(x)));
}

// per-float4 align contribution (att + ga masked sums)
__device__ __forceinline__ void align_elem(float4 a, int idx,
                                           const int* __restrict__ s_li,
                                           const int* __restrict__ s_lo,
                                           float& s_att, float& s_ga) {
    unsigned uidx = (unsigned)idx;
    unsigned j4  = uidx % TIN4;
    unsigned row = uidx / TIN4;
    unsigned b   = row / TOUT;
    int      i   = (int)(row - b * TOUT);
    int      j0  = (int)(j4 << 2);

    float sfull = (a.x + a.y) + (a.z + a.w);

    // att: sum over j < i
    if (j0 + 4 <= i) {
        s_att += sfull;
    } else if (j0 < i) {
        s_att += ((j0     < i ? a.x : 0.0f) + (j0 + 1 < i ? a.y : 0.0f))
               + ((j0 + 2 < i ? a.z : 0.0f) + (j0 + 3 < i ? a.w : 0.0f));
    }

    // ga main: valid region (i<lo, j<li); w==1 outside the narrow exp band
    int limG = (i < s_lo[b]) ? s_li[b] : 0;
    if (j0 + 4 <= limG) {
        s_ga += sfull;
    } else if (j0 < limG) {
        s_ga += ((j0     < limG ? a.x : 0.0f) + (j0 + 1 < limG ? a.y : 0.0f))
              + ((j0 + 2 < limG ? a.z : 0.0f) + (j0 + 3 < limG ? a.w : 0.0f));
    }
}

// guided-attention band correction for this thread's row stripe:
// sum a*exp(-d^2/(2 sigma^2)); only |i - j*lo/li| <= BAND contributes.
__device__ __forceinline__ float corr_phase(const float* __restrict__ al_s,
                                            const int* __restrict__ s_li,
                                            const int* __restrict__ s_lo,
                                            int gtid) {
    float s_corr = 0.0f;
    for (int row = gtid; row < N_ROWS; row += TSTRIDE) {
        int b = row / TOUT;
        int i = row - b * TOUT;
        int li = s_li[b];
        int lo = s_lo[b];
        if (i < lo) {
            float fli = (float)li, flo = (float)lo, fi = (float)i;
            float inv_scale = __fdividef(fli, flo);   // li/lo
            float scale     = __fdividef(flo, fli);   // lo/li
            int j0c = (int)floorf((fi - BAND) * inv_scale);
            const float* rp = al_s + (long)row * TIN;
            #pragma unroll
            for (int k = 0; k < 4; k++) {
                int j = j0c + k;
                if (j >= 0 && j < li) {
                    float d = fmaf((float)j, -scale, fi);
                    float e = __expf(-d * d * INV2SIG2);
                    s_corr += __ldg(&rp[j]) * e;
                }
            }
        }
    }
    return s_corr;
}

__global__ void __launch_bounds__(NTHREAD, 5)
fused_kernel(const float4* __restrict__ mo,
             const float4* __restrict__ mp,
             const float4* __restrict__ mt,
             const float4* __restrict__ go,
             const float4* __restrict__ gt,
             const float4* __restrict__ al,
             const float*  __restrict__ al_s,
             const int*    __restrict__ in_len,
             const int*    __restrict__ out_len,
             float*        __restrict__ out) {
    __shared__ int s_li[B_], s_lo[B_];
    if (threadIdx.x < B_) {
        s_li[threadIdx.x] = in_len[threadIdx.x];
        s_lo[threadIdx.x] = out_len[threadIdx.x];
    }
    __syncthreads();

    const int  gtid = blockIdx.x * NTHREAD + threadIdx.x;
    const bool even = (blockIdx.x & 1) == 0;

    // ======== Phase 1: Gate BCE (tiny) ========
    float s_gate = 0.0f;
    for (int i = gtid; i < N_GATE4; i += TSTRIDE) {
        float4 x = __ldcs(&go[i]);
        float4 z = __ldcs(&gt[i]);
        s_gate += bce1(x.x, z.x) + bce1(x.y, z.y) + bce1(x.z, z.z) + bce1(x.w, z.w);
    }

    // ======== Phase 2: Mel L1 (decoder + postnet), 2x unrolled, streaming ========
    float s1 = 0.0f, s2 = 0.0f;
    {
        int i = gtid;
        for (; i + TSTRIDE < N_MEL4; i += 2 * TSTRIDE) {
            float4 a0 = __ldcs(&mo[i]), a1 = __ldcs(&mo[i + TSTRIDE]);
            float4 t0 = __ldcs(&mt[i]), t1 = __ldcs(&mt[i + TSTRIDE]);
            float4 p0 = __ldcs(&mp[i]), p1 = __ldcs(&mp[i + TSTRIDE]);
            s1 += fabsf(a0.x - t0.x) + fabsf(a0.y - t0.y) + fabsf(a0.z - t0.z) + fabsf(a0.w - t0.w);
            s2 += fabsf(p0.x - t0.x) + fabsf(p0.y - t0.y) + fabsf(p0.z - t0.z) + fabsf(p0.w - t0.w);
            s1 += fabsf(a1.x - t1.x) + fabsf(a1.y - t1.y) + fabsf(a1.z - t1.z) + fabsf(a1.w - t1.w);
            s2 += fabsf(p1.x - t1.x) + fabsf(p1.y - t1.y) + fabsf(p1.z - t1.z) + fabsf(p1.w - t1.w);
        }
        for (; i < N_MEL4; i += TSTRIDE) {
            float4 a = __ldcs(&mo[i]), p = __ldcs(&mp[i]), t = __ldcs(&mt[i]);
            s1 += fabsf(a.x - t.x) + fabsf(a.y - t.y) + fabsf(a.z - t.z) + fabsf(a.w - t.w);
            s2 += fabsf(p.x - t.x) + fabsf(p.y - t.y) + fabsf(p.z - t.z) + fabsf(p.w - t.w);
        }
    }

    // ======== Phase 3a: corr (even blocks) — staggered latency-bound phase ========
    float s_corr = 0.0f;
    if (even) s_corr = corr_phase(al_s, s_li, s_lo, gtid);

    // ======== Phase 4: Alignments main pass, 6-deep batched LDG.128 ========
    // 6 x 128B outstanding per warp x 40 warps/SM = 30.7KB in flight/SM,
    // above the ~25.6KB BW*latency requirement.
    float s_att = 0.0f, s_ga = 0.0f;
    {
        int idx = gtid;
        for (; idx + 5 * TSTRIDE < N_AL4; idx += 6 * TSTRIDE) {
            float4 a0 = __ldcs(&al[idx]);
            float4 a1 = __ldcs(&al[idx + TSTRIDE]);
            float4 a2 = __ldcs(&al[idx + 2 * TSTRIDE]);
            float4 a3 = __ldcs(&al[idx + 3 * TSTRIDE]);
            float4 a4 = __ldcs(&al[idx + 4 * TSTRIDE]);
            float4 a5 = __ldcs(&al[idx + 5 * TSTRIDE]);
            align_elem(a0, idx,               s_li, s_lo, s_att, s_ga);
            align_elem(a1, idx + TSTRIDE,     s_li, s_lo, s_att, s_ga);
            align_elem(a2, idx + 2 * TSTRIDE, s_li, s_lo, s_att, s_ga);
            align_elem(a3, idx + 3 * TSTRIDE, s_li, s_lo, s_att, s_ga);
            align_elem(a4, idx + 4 * TSTRIDE, s_li, s_lo, s_att, s_ga);
            align_elem(a5, idx + 5 * TSTRIDE, s_li, s_lo, s_att, s_ga);
        }
        for (; idx < N_AL4; idx += TSTRIDE) {
            float4 a = __ldcs(&al[idx]);
            align_elem(a, idx, s_li, s_lo, s_att, s_ga);
        }
    }

    // ======== Phase 3b: corr (odd blocks) ========
    if (!even) s_corr = corr_phase(al_s, s_li, s_lo, gtid);

    s_ga -= s_corr;

    // ======== Block reduce all 5 sums, atomics, last-block finalize ========
    __shared__ float sh[5][8];
    int lane = threadIdx.x & 31;
    int wid  = threadIdx.x >> 5;
    float v0 = warp_sum(s1);
    float v1 = warp_sum(s2);
    float v2 = warp_sum(s_gate);
    float v3 = warp_sum(s_att);
    float v4 = warp_sum(s_ga);
    if (lane == 0) {
        sh[0][wid] = v0; sh[1][wid] = v1; sh[2][wid] = v2;
        sh[3][wid] = v3; sh[4][wid] = v4;
    }
    __syncthreads();
    if (wid == 0) {
        v0 = warp_sum((lane < 8) ? sh[0][lane] : 0.0f);
        v1 = warp_sum((lane < 8) ? sh[1][lane] : 0.0f);
        v2 = warp_sum((lane < 8) ? sh[2][lane] : 0.0f);
        v3 = warp_sum((lane < 8) ? sh[3][lane] : 0.0f);
        v4 = warp_sum((lane < 8) ? sh[4][lane] : 0.0f);
        if (lane == 0) {
            atomicAdd(&g_acc[0], (double)v0);
            atomicAdd(&g_acc[1], (double)v1);
            atomicAdd(&g_acc[2], (double)v2);
            atomicAdd(&g_acc[3], (double)v3);
            atomicAdd(&g_acc[4], (double)v4);
            __threadfence();
            unsigned int t = atomicAdd(&g_done, 1u);
            if (t == (unsigned)(G_TOTAL - 1)) {
                volatile double* acc = g_acc;
                double mel  = (acc[0] + acc[1]) / (double)N_MEL;
                double gate = acc[2] / (double)N_GATE;
                double att  = acc[3] / (double)B_;
                double ga   = acc[4] / (double)B_;
                double total = mel + gate + 0.1 * att + 0.1 * ga;
                out[0] = (float)total;
                out[1] = (float)mel;
                out[2] = (float)gate;
                out[3] = (float)att;
                out[4] = (float)ga;
                acc[0] = 0.0; acc[1] = 0.0; acc[2] = 0.0; acc[3] = 0.0; acc[4] = 0.0;
                g_done = 0u;
                __threadfence();
            }
        }
    }
}

extern "C" void kernel_launch(void* const* d_in, const int* in_sizes, int n_in,
                              void* d_out, int out_size) {
    const float* mel_out         = (const float*)d_in[0];
    const float* mel_out_postnet = (const float*)d_in[1];
    const float* gate_out        = (const float*)d_in[2];
    const float* alignments      = (const float*)d_in[3];
    const float* mel_target      = (const float*)d_in[4];
    const float* gate_target     = (const float*)d_in[5];
    const int*   input_lengths   = (const int*)d_in[6];
    const int*   output_lengths  = (const int*)d_in[7];
    float* out = (float*)d_out;

    fused_kernel<<<G_TOTAL, NTHREAD>>>((const float4*)mel_out,
                                       (const float4*)mel_out_postnet,
                                       (const float4*)mel_target,
                                       (const float4*)gate_out,
                                       (const float4*)gate_target,
                                       (const float4*)alignments,
                                       alignments,
                                       input_lengths, output_lengths,
                                       out);
}